// round 1
// baseline (speedup 1.0000x reference)
#include <cuda_runtime.h>

namespace {
constexpr int B = 16;
constexpr int L = 1024;
constexpr int H = 512;
constexpr int V = 32000;
constexpr int HALF = 256;
constexpr int TOK = B * L;           // 16384
constexpr float ALPHA_C = 0.05f;     // 1 - 0.95
constexpr float EPS_LN_C = 1e-5f;
constexpr float EPS_NORM_C = 1e-12f;
}

// ---------------- scratch (static device globals; no allocation) ----------------
__device__ float g_h0[TOK * H];            // embed gather output     (32 MB)
__device__ float g_ff1[TOK * 2 * H];       // FFN hidden              (64 MB)
__device__ float g_y2[TOK * H];            // FFN output (pre-LN)     (32 MB)
__device__ float g_h[TOK * H];             // post-LN hidden          (32 MB)
__device__ float g_kn[2 * L * B * HALF];   // keys -> normalized keys (32 MB), layout [m][l][b][i]
__device__ float g_nrm[2 * L * B];         // clamped norms, layout [m][l][b]
__device__ float g_c[B * H];               // context  [b][m*HALF+i]
__device__ float g_r[B * H];               // readout projection

// ---------------- embedding gather ----------------
__global__ void k_gather(const int* __restrict__ seq, const float* __restrict__ embed,
                         float* __restrict__ out) {
    int t = blockIdx.x;                    // token index (b*L + l)
    int v = seq[t];
    const float4* src = reinterpret_cast<const float4*>(embed + (size_t)v * H);
    float4* dst = reinterpret_cast<float4*>(out + (size_t)t * H);
    dst[threadIdx.x] = src[threadIdx.x];   // 128 threads * float4 = 512 floats
}

// ---------------- fp32 SGEMM: C[m,n] = A[m,:] . W[n,:] (+bias) (+relu / keyproj scatter) ---
// MODE 0: +bias; MODE 1: +bias, relu; MODE 2: no bias, scatter to [l][b][n] layout
template <int MODE>
__global__ void __launch_bounds__(256) k_gemm(const float* __restrict__ A,
                                              const float* __restrict__ W,
                                              const float* __restrict__ bias,
                                              float* __restrict__ C,
                                              int M, int N, int K) {
    __shared__ float As[8][128 + 4];
    __shared__ float Bs[8][128 + 4];
    const int tid = threadIdx.x;
    const int bm = blockIdx.y * 128;
    const int bn = blockIdx.x * 128;
    const int tr = tid >> 4;       // 0..15
    const int tc = tid & 15;       // 0..15
    const int lrow = tid >> 1;     // 0..127
    const int lc4 = (tid & 1) * 4; // 0 or 4

    const float* Ap = A + (size_t)(bm + lrow) * K + lc4;
    const float* Wp = W + (size_t)(bn + lrow) * K + lc4;

    float acc[8][8];
#pragma unroll
    for (int i = 0; i < 8; ++i)
#pragma unroll
        for (int j = 0; j < 8; ++j) acc[i][j] = 0.f;

    for (int kt = 0; kt < K; kt += 8) {
        float4 av = *reinterpret_cast<const float4*>(Ap + kt);
        float4 wv = *reinterpret_cast<const float4*>(Wp + kt);
        As[lc4 + 0][lrow] = av.x; As[lc4 + 1][lrow] = av.y;
        As[lc4 + 2][lrow] = av.z; As[lc4 + 3][lrow] = av.w;
        Bs[lc4 + 0][lrow] = wv.x; Bs[lc4 + 1][lrow] = wv.y;
        Bs[lc4 + 2][lrow] = wv.z; Bs[lc4 + 3][lrow] = wv.w;
        __syncthreads();
#pragma unroll
        for (int kk = 0; kk < 8; ++kk) {
            float a[8], bb[8];
            *reinterpret_cast<float4*>(&a[0]) = *reinterpret_cast<const float4*>(&As[kk][tr * 8]);
            *reinterpret_cast<float4*>(&a[4]) = *reinterpret_cast<const float4*>(&As[kk][tr * 8 + 4]);
            *reinterpret_cast<float4*>(&bb[0]) = *reinterpret_cast<const float4*>(&Bs[kk][tc * 8]);
            *reinterpret_cast<float4*>(&bb[4]) = *reinterpret_cast<const float4*>(&Bs[kk][tc * 8 + 4]);
#pragma unroll
            for (int i = 0; i < 8; ++i)
#pragma unroll
                for (int j = 0; j < 8; ++j) acc[i][j] += a[i] * bb[j];
        }
        __syncthreads();
    }

    if (MODE == 2) {
        // scatter: token row t -> (b = t>>10, l = t&1023), dst = ((l*B + b)*HALF + n)
#pragma unroll
        for (int i = 0; i < 8; ++i) {
            int grow = bm + tr * 8 + i;
            int b_ = grow >> 10;
            int l_ = grow & 1023;
            float* dst = C + ((size_t)l_ * B + b_) * HALF + bn + tc * 8;
            float4 o0 = make_float4(acc[i][0], acc[i][1], acc[i][2], acc[i][3]);
            float4 o1 = make_float4(acc[i][4], acc[i][5], acc[i][6], acc[i][7]);
            *reinterpret_cast<float4*>(dst) = o0;
            *reinterpret_cast<float4*>(dst + 4) = o1;
        }
    } else {
        float bv[8];
#pragma unroll
        for (int j = 0; j < 8; ++j) bv[j] = bias[bn + tc * 8 + j];
#pragma unroll
        for (int i = 0; i < 8; ++i) {
            float o[8];
#pragma unroll
            for (int j = 0; j < 8; ++j) {
                float v = acc[i][j] + bv[j];
                if (MODE == 1) v = fmaxf(v, 0.f);
                o[j] = v;
            }
            float* dst = C + (size_t)(bm + tr * 8 + i) * N + bn + tc * 8;
            *reinterpret_cast<float4*>(dst) = make_float4(o[0], o[1], o[2], o[3]);
            *reinterpret_cast<float4*>(dst + 4) = make_float4(o[4], o[5], o[6], o[7]);
        }
    }
}

// ---------------- residual + LayerNorm (warp per row) ----------------
__global__ void k_ln(const float* __restrict__ y2, const float* __restrict__ h0,
                     const float* __restrict__ gamma, const float* __restrict__ beta,
                     float* __restrict__ out) {
    int warp = threadIdx.x >> 5, lane = threadIdx.x & 31;
    int row = blockIdx.x * 8 + warp;
    const float4* a = reinterpret_cast<const float4*>(y2 + (size_t)row * H);
    const float4* hb = reinterpret_cast<const float4*>(h0 + (size_t)row * H);
    float x[16];
    float s = 0.f, s2 = 0.f;
#pragma unroll
    for (int i = 0; i < 4; ++i) {
        float4 u = a[lane + i * 32];
        float4 v = hb[lane + i * 32];
        float t0 = u.x + v.x, t1 = u.y + v.y, t2 = u.z + v.z, t3 = u.w + v.w;
        x[i * 4 + 0] = t0; x[i * 4 + 1] = t1; x[i * 4 + 2] = t2; x[i * 4 + 3] = t3;
        s += t0 + t1 + t2 + t3;
        s2 += t0 * t0 + t1 * t1 + t2 * t2 + t3 * t3;
    }
#pragma unroll
    for (int off = 16; off > 0; off >>= 1) {
        s += __shfl_xor_sync(0xffffffffu, s, off);
        s2 += __shfl_xor_sync(0xffffffffu, s2, off);
    }
    float mu = s * (1.f / H);
    float var = s2 * (1.f / H) - mu * mu;
    float rstd = rsqrtf(var + EPS_LN_C);
    float4* o = reinterpret_cast<float4*>(out + (size_t)row * H);
    const float4* g4 = reinterpret_cast<const float4*>(gamma);
    const float4* b4 = reinterpret_cast<const float4*>(beta);
#pragma unroll
    for (int i = 0; i < 4; ++i) {
        float4 gg = __ldg(g4 + lane + i * 32);
        float4 bb = __ldg(b4 + lane + i * 32);
        float4 r;
        r.x = (x[i * 4 + 0] - mu) * rstd * gg.x + bb.x;
        r.y = (x[i * 4 + 1] - mu) * rstd * gg.y + bb.y;
        r.z = (x[i * 4 + 2] - mu) * rstd * gg.z + bb.z;
        r.w = (x[i * 4 + 3] - mu) * rstd * gg.w + bb.w;
        o[lane + i * 32] = r;
    }
}

// ---------------- L2-normalize key rows in place, save clamped norm ----------------
__global__ void k_norm(float* __restrict__ kn, float* __restrict__ nrm) {
    int warp = threadIdx.x >> 5, lane = threadIdx.x & 31;
    int row = blockIdx.x * 8 + warp;               // 0 .. 2*L*B-1
    float4* p4 = reinterpret_cast<float4*>(kn + (size_t)row * HALF);
    float4 v0 = p4[lane];
    float4 v1 = p4[lane + 32];
    float s = v0.x * v0.x + v0.y * v0.y + v0.z * v0.z + v0.w * v0.w
            + v1.x * v1.x + v1.y * v1.y + v1.z * v1.z + v1.w * v1.w;
#pragma unroll
    for (int off = 16; off > 0; off >>= 1) s += __shfl_xor_sync(0xffffffffu, s, off);
    float n = sqrtf(s);
    float nc = fmaxf(n, EPS_NORM_C);
    float inv = 1.f / nc;
    v0.x *= inv; v0.y *= inv; v0.z *= inv; v0.w *= inv;
    v1.x *= inv; v1.y *= inv; v1.z *= inv; v1.w *= inv;
    p4[lane] = v0;
    p4[lane + 32] = v1;
    if (lane == 0) nrm[row] = nc;
}

// ---------------- the EMA scan: warp handles 8 independent M-rows ----------------
// rows of M evolve independently: M_i += 0.05*(kn_i*|k| - M_i.kn) * kn
__global__ void __launch_bounds__(128) k_scan(const float* __restrict__ kn_all,
                                              const float* __restrict__ nrm_all,
                                              float* __restrict__ cbuf) {
    const int lane = threadIdx.x & 31;
    const int warp = threadIdx.x >> 5;
    const int pair = blockIdx.x >> 3;      // 0..31 : (m,b)
    const int cta8 = blockIdx.x & 7;
    const int m = pair >> 4;
    const int b = pair & 15;
    const int grp = cta8 * 4 + warp;       // row group 0..31
    const int r0 = grp * 8;

    const float* __restrict__ kn = kn_all + ((size_t)m * L * B + b) * HALF;
    const float* __restrict__ nr = nrm_all + (size_t)m * L * B + b;

    float Mx[8][8];
#pragma unroll
    for (int r = 0; r < 8; ++r)
#pragma unroll
        for (int q = 0; q < 8; ++q) Mx[r][q] = 0.f;

    float k[8];
    float nrm;
    {
        const float4* p = reinterpret_cast<const float4*>(kn + lane * 8);
        float4 u = __ldg(p), v = __ldg(p + 1);
        k[0] = u.x; k[1] = u.y; k[2] = u.z; k[3] = u.w;
        k[4] = v.x; k[5] = v.y; k[6] = v.z; k[7] = v.w;
        nrm = __ldg(nr);
    }

    for (int t = 0; t < L - 1; ++t) {
        float cur[8];
#pragma unroll
        for (int q = 0; q < 8; ++q) cur[q] = k[q];
        float cn = nrm;
        {   // prefetch step t+1 (valid up to t+1 = L-1, used by the final query)
            const float4* p = reinterpret_cast<const float4*>(
                kn + (size_t)(t + 1) * (B * HALF) + lane * 8);
            float4 u = __ldg(p), v = __ldg(p + 1);
            k[0] = u.x; k[1] = u.y; k[2] = u.z; k[3] = u.w;
            k[4] = v.x; k[5] = v.y; k[6] = v.z; k[7] = v.w;
            nrm = __ldg(nr + (size_t)(t + 1) * B);
        }
        float dot[8];
#pragma unroll
        for (int r = 0; r < 8; ++r) {
            float d = Mx[r][0] * cur[0];
#pragma unroll
            for (int q = 1; q < 8; ++q) d += Mx[r][q] * cur[q];
            dot[r] = d;
        }
#pragma unroll
        for (int off = 16; off > 0; off >>= 1)
#pragma unroll
            for (int r = 0; r < 8; ++r)
                dot[r] += __shfl_xor_sync(0xffffffffu, dot[r], off);
#pragma unroll
        for (int r = 0; r < 8; ++r) {
            float kni = __shfl_sync(0xffffffffu, cur[r], grp); // kn[r0+r]
            float coef = ALPHA_C * (kni * cn - dot[r]);
#pragma unroll
            for (int q = 0; q < 8; ++q) Mx[r][q] += coef * cur[q];
        }
    }

    // query with unnormalized last key: c_i = (M_i . kn(L-1)) * nrm(L-1)
    float dot[8];
#pragma unroll
    for (int r = 0; r < 8; ++r) {
        float d = Mx[r][0] * k[0];
#pragma unroll
        for (int q = 1; q < 8; ++q) d += Mx[r][q] * k[q];
        dot[r] = d;
    }
#pragma unroll
    for (int off = 16; off > 0; off >>= 1)
#pragma unroll
        for (int r = 0; r < 8; ++r)
            dot[r] += __shfl_xor_sync(0xffffffffu, dot[r], off);
    if (lane == 0) {
#pragma unroll
        for (int r = 0; r < 8; ++r)
            cbuf[b * H + m * HALF + r0 + r] = dot[r] * nrm;
    }
}

// ---------------- r = c @ rp_w^T + rp_b  ([16,512] x [512,512]) ----------------
__global__ void k_rp(const float* __restrict__ c, const float* __restrict__ W,
                     const float* __restrict__ bias, float* __restrict__ r) {
    __shared__ float cs[B * (H + 1)];
    for (int i = threadIdx.x; i < B * H; i += 256) {
        int bb = i >> 9, hh = i & 511;
        cs[bb * (H + 1) + hh] = c[i];
    }
    __syncthreads();
    int g = blockIdx.x * 16 + (threadIdx.x >> 4);
    int b = threadIdx.x & 15;
    const float* w = W + (size_t)g * H;
    const float* cb = &cs[b * (H + 1)];
    float acc = 0.f;
    for (int h = 0; h < H; h += 4) {
        float4 wv = __ldg(reinterpret_cast<const float4*>(w + h));
        acc += cb[h] * wv.x + cb[h + 1] * wv.y + cb[h + 2] * wv.z + cb[h + 3] * wv.w;
    }
    r[b * H + g] = acc + bias[g];
}

// ---------------- out = r @ out_w^T + out_b  ([16,512] x [32000,512]) ----------------
__global__ void k_out(const float* __restrict__ r, const float* __restrict__ W,
                      const float* __restrict__ bias, float* __restrict__ out) {
    __shared__ float rs[B * H];
    for (int i = threadIdx.x; i < B * H; i += 256) rs[i] = r[i];
    __syncthreads();
    int v = blockIdx.x * 256 + threadIdx.x;
    float acc[B];
#pragma unroll
    for (int b = 0; b < B; ++b) acc[b] = 0.f;
    const float4* w = reinterpret_cast<const float4*>(W + (size_t)v * H);
#pragma unroll 4
    for (int i = 0; i < H / 4; ++i) {
        float4 wv = __ldg(w + i);
#pragma unroll
        for (int b = 0; b < B; ++b) {
            float4 rv = *reinterpret_cast<const float4*>(&rs[b * H + i * 4]);
            acc[b] += rv.x * wv.x + rv.y * wv.y + rv.z * wv.z + rv.w * wv.w;
        }
    }
    float bb = __ldg(bias + v);
#pragma unroll
    for (int b = 0; b < B; ++b) out[(size_t)b * V + v] = acc[b] + bb;
}

// ---------------- launch ----------------
extern "C" void kernel_launch(void* const* d_in, const int* in_sizes, int n_in,
                              void* d_out, int out_size) {
    const int*   seq   = (const int*)d_in[0];
    const float* embed = (const float*)d_in[1];
    const float* ff_w1 = (const float*)d_in[2];
    const float* ff_b1 = (const float*)d_in[3];
    const float* ff_w2 = (const float*)d_in[4];
    const float* ff_b2 = (const float*)d_in[5];
    const float* gamma = (const float*)d_in[6];
    const float* beta  = (const float*)d_in[7];
    const float* sem_w = (const float*)d_in[8];
    const float* epi_w = (const float*)d_in[9];
    const float* rp_w  = (const float*)d_in[10];
    const float* rp_b  = (const float*)d_in[11];
    const float* out_w = (const float*)d_in[12];
    const float* out_b = (const float*)d_in[13];
    float* out = (float*)d_out;

    float *h0, *ff1, *y2, *h, *kn, *nrm, *c, *r;
    cudaGetSymbolAddress((void**)&h0,  g_h0);
    cudaGetSymbolAddress((void**)&ff1, g_ff1);
    cudaGetSymbolAddress((void**)&y2,  g_y2);
    cudaGetSymbolAddress((void**)&h,   g_h);
    cudaGetSymbolAddress((void**)&kn,  g_kn);
    cudaGetSymbolAddress((void**)&nrm, g_nrm);
    cudaGetSymbolAddress((void**)&c,   g_c);
    cudaGetSymbolAddress((void**)&r,   g_r);

    // 1. embedding gather
    k_gather<<<TOK, 128>>>(seq, embed, h0);
    // 2. FFN up (relu)
    k_gemm<1><<<dim3(2 * H / 128, TOK / 128), 256>>>(h0, ff_w1, ff_b1, ff1, TOK, 2 * H, H);
    // 3. FFN down
    k_gemm<0><<<dim3(H / 128, TOK / 128), 256>>>(ff1, ff_w2, ff_b2, y2, TOK, H, 2 * H);
    // 4. residual + layernorm
    k_ln<<<TOK / 8, 256>>>(y2, h0, gamma, beta, h);
    // 5+6. key projections, scattered to [l][b][c]
    k_gemm<2><<<dim3(HALF / 128, TOK / 128), 256>>>(h, sem_w, nullptr, kn, TOK, HALF, H);
    k_gemm<2><<<dim3(HALF / 128, TOK / 128), 256>>>(h, epi_w, nullptr,
                                                    kn + (size_t)L * B * HALF, TOK, HALF, H);
    // 7. normalize keys in place, stash clamped norms
    k_norm<<<(2 * L * B) / 8, 256>>>(kn, nrm);
    // 8. the sequential scan (row-parallel)
    k_scan<<<256, 128>>>(kn, nrm, c);
    // 9. readout projection
    k_rp<<<H / 16, 256>>>(c, rp_w, rp_b, r);
    // 10. logits
    k_out<<<V / 256, 256>>>(r, out_w, out_b, out);
}